// round 8
// baseline (speedup 1.0000x reference)
#include <cuda_runtime.h>

// SoftCLDiceLoss on [8,2,1024,1024]:
//   p = sigmoid(pred), t = target
//   skel(x) = 1 - prod_{k=0..10} (1 - relu(E_k - dilate(E_{k+1}))),  E_k = erode^k(clip(x))
//   erode = 3x3 min (pad +inf), dilate = 3x3 max (pad -inf)
//   tprec = sum(skel_p*t)/(sum(skel_p)+eps); tsens = sum(skel_t*p)/(sum(skel_t)+eps)
//   loss = mean(1 - 2*tprec*tsens/(tprec+tsens+eps))
//
// R6: 2 columns per lane (64-col warp strips), pair-shuffle horizontal taps,
// interior tiles take a mask-free fast path. 3 erosion steps fused per kernel,
// final 2 steps fused with the reduction. Depth-4 prefetch pipelines.

#define IMG_W    1024
#define IMG_H    1024
#define NPLANES  16
#define PLANE_SZ (IMG_W * IMG_H)

#define STRIP    128
#define TCOLS    56            // useful cols per warp (64 - 2*4 halo)
#define NTILES   19            // ceil(1024/56)

__device__ float g_E[2][2][NPLANES * PLANE_SZ];   // [skel][pingpong]
__device__ float g_acc[2][NPLANES * PLANE_SZ];
__device__ float g_sums[NPLANES * 4];

__device__ __forceinline__ float min3f(float a, float b, float c) { return fminf(a, fminf(b, c)); }
__device__ __forceinline__ float max3f(float a, float b, float c) { return fmaxf(a, fmaxf(b, c)); }
__device__ __forceinline__ float sigmoidf(float x) { return 1.0f / (1.0f + __expf(-x)); }

// Pair horizontal 3-taps: lane holds cols (2l, 2l+1). 2 shuffles + 3 ops -> 2 results.
__device__ __forceinline__ void hpmin(const float v[2], float o[2]) {
    float m  = fminf(v[0], v[1]);
    float vl = __shfl_up_sync(0xffffffffu, v[1], 1);
    float vr = __shfl_down_sync(0xffffffffu, v[0], 1);
    o[0] = fminf(vl, m);
    o[1] = fminf(m, vr);
}
__device__ __forceinline__ void hpmax(const float v[2], float o[2]) {
    float m  = fmaxf(v[0], v[1]);
    float vl = __shfl_up_sync(0xffffffffu, v[1], 1);
    float vr = __shfl_down_sync(0xffffffffu, v[0], 1);
    o[0] = fmaxf(vl, m);
    o[1] = fmaxf(m, vr);
}

__global__ void zero_sums_kernel() {
    int i = threadIdx.x;
    if (i < NPLANES * 4) g_sums[i] = 0.0f;
}

// ---------------------------------------------------------------------------
// Triple sweep: reads E_k, writes E_{k+3}, acc *= prod (1-delta_{k..k+2}).
// Col validity by depth d: cols [d, 63-d]; outputs cols [4,59] = lanes 2..29.
// ---------------------------------------------------------------------------
template<bool FIRST, bool MASK>
__device__ __forceinline__ void triple_sweep(
    const float* __restrict__ src,
    float* __restrict__ dst,
    float* __restrict__ acc,
    int skel, int gx0, int y0, int lane)
{
    const int  yEnd = y0 + STRIP;
    const bool outL = (lane >= 2) & (lane <= 29);
    bool inc[2];
    inc[0] = !MASK || ((unsigned)gx0       < (unsigned)IMG_W);
    inc[1] = !MASK || ((unsigned)(gx0 + 1) < (unsigned)IMG_W);

    float h1m1[2]={}, h1m2[2]={}, h1dm1[2]={}, h1dm2[2]={};
    float h2m1[2]={}, h2m2[2]={}, h2dm1[2]={}, h2dm2[2]={};
    float h3m1[2]={}, h3m2[2]={}, h3dm1[2]={}, h3dm2[2]={};
    float ad1[2]={}, ad2[2]={}, e1d1[2]={}, e1d2[2]={}, e2d1[2]={}, e2d2[2]={};
    float mk0d1[2]={}, mk0d2[2]={}, mk1d1[2]={};

    float abuf[4][2];
    float accbuf[4][2] = {};

    auto ldrow = [&](int rr, float v[2]) {
        if (MASK) {
            v[0] = 1e30f; v[1] = 1e30f;
            bool rv = (unsigned)rr < (unsigned)IMG_H;
            if (rv & inc[0]) {
                float x = __ldg(&src[(size_t)rr * IMG_W + gx0]);
                v[0] = FIRST ? (skel ? __saturatef(x) : sigmoidf(x)) : x;
            }
            if (rv & inc[1]) {
                float x = __ldg(&src[(size_t)rr * IMG_W + gx0 + 1]);
                v[1] = FIRST ? (skel ? __saturatef(x) : sigmoidf(x)) : x;
            }
        } else {
            float2 t = *reinterpret_cast<const float2*>(&src[(size_t)rr * IMG_W + gx0]);
            v[0] = FIRST ? (skel ? __saturatef(t.x) : sigmoidf(t.x)) : t.x;
            v[1] = FIRST ? (skel ? __saturatef(t.y) : sigmoidf(t.y)) : t.y;
        }
    };

    #pragma unroll
    for (int j = 0; j < 4; j++) ldrow(y0 - 4 + j, abuf[j]);

    for (int rb = y0 - 4; rb <= yEnd; rb += 4) {
        #pragma unroll
        for (int j = 0; j < 4; j++) {
            const int r = rb + j;
            float a[2] = { abuf[j][0], abuf[j][1] };
            ldrow(r + 4, abuf[j]);                        // consumed 4 iters later
            float av[2] = { 0.f, 0.f };
            if (!FIRST) {
                av[0] = accbuf[j][0]; av[1] = accbuf[j][1];   // acc row r-4
                if ((r >= y0) & (r < yEnd) & outL) {
                    if (MASK) {
                        if (inc[0]) accbuf[j][0] = acc[(size_t)r * IMG_W + gx0];
                        if (inc[1]) accbuf[j][1] = acc[(size_t)r * IMG_W + gx0 + 1];
                    } else {
                        float2 t = *reinterpret_cast<const float2*>(&acc[(size_t)r * IMG_W + gx0]);
                        accbuf[j][0] = t.x; accbuf[j][1] = t.y;
                    }
                }
            }

            float h1[2]; hpmin(a, h1);                    // row r
            float e1[2], e1dv[2], e1ev[2];
            const bool m1 = !MASK || ((unsigned)(r - 1) < (unsigned)IMG_H);
            #pragma unroll
            for (int c = 0; c < 2; c++) {
                e1[c] = min3f(h1m2[c], h1m1[c], h1[c]);   // E_{k+1}, row r-1
                bool mm = m1 & inc[c];
                e1dv[c] = mm ? e1[c] : -1e30f;
                e1ev[c] = mm ? e1[c] :  1e30f;
            }
            float h1d[2]; hpmax(e1dv, h1d);               // row r-1
            float h2[2];  hpmin(e1ev, h2);                // row r-1
            float e2[2], e2dv[2], e2ev[2], mk0[2];
            const bool m2 = !MASK || ((unsigned)(r - 2) < (unsigned)IMG_H);
            #pragma unroll
            for (int c = 0; c < 2; c++) {
                float d1 = max3f(h1dm2[c], h1dm1[c], h1d[c]);  // dilate(E_{k+1}), r-2
                mk0[c] = 1.f - fmaxf(ad2[c] - d1, 0.f);        // 1-delta_k, r-2
                e2[c] = min3f(h2m2[c], h2m1[c], h2[c]);        // E_{k+2}, r-2
                bool mm = m2 & inc[c];
                e2dv[c] = mm ? e2[c] : -1e30f;
                e2ev[c] = mm ? e2[c] :  1e30f;
            }
            float h2d[2]; hpmax(e2dv, h2d);               // r-2
            float h3[2];  hpmin(e2ev, h3);                // r-2
            float e3[2], e3dv[2], mk1[2];
            const bool m3 = !MASK || ((unsigned)(r - 3) < (unsigned)IMG_H);
            #pragma unroll
            for (int c = 0; c < 2; c++) {
                float d2 = max3f(h2dm2[c], h2dm1[c], h2d[c]);  // dilate(E_{k+2}), r-3
                mk1[c] = 1.f - fmaxf(e1d2[c] - d2, 0.f);       // 1-delta_{k+1}, r-3
                e3[c] = min3f(h3m2[c], h3m1[c], h3[c]);        // E_{k+3}, r-3
                bool mm = m3 & inc[c];
                e3dv[c] = mm ? e3[c] : -1e30f;
            }
            if (outL & (r - 3 >= y0) & (r - 3 < yEnd)) {
                if (MASK) {
                    if (inc[0]) dst[(size_t)(r - 3) * IMG_W + gx0]     = e3[0];
                    if (inc[1]) dst[(size_t)(r - 3) * IMG_W + gx0 + 1] = e3[1];
                } else {
                    *reinterpret_cast<float2*>(&dst[(size_t)(r - 3) * IMG_W + gx0]) =
                        make_float2(e3[0], e3[1]);
                }
            }
            float h3d[2]; hpmax(e3dv, h3d);               // r-3
            float mval[2];
            #pragma unroll
            for (int c = 0; c < 2; c++) {
                float d3  = max3f(h3dm2[c], h3dm1[c], h3d[c]); // dilate(E_{k+3}), r-4
                float mk2 = 1.f - fmaxf(e2d2[c] - d3, 0.f);    // 1-delta_{k+2}, r-4
                mval[c] = mk0d2[c] * mk1d1[c] * mk2;
                if (!FIRST) mval[c] *= av[c];
            }
            const int ro = r - 4;
            if (outL & (ro >= y0) & (ro < yEnd)) {
                if (MASK) {
                    if (inc[0]) acc[(size_t)ro * IMG_W + gx0]     = mval[0];
                    if (inc[1]) acc[(size_t)ro * IMG_W + gx0 + 1] = mval[1];
                } else {
                    *reinterpret_cast<float2*>(&acc[(size_t)ro * IMG_W + gx0]) =
                        make_float2(mval[0], mval[1]);
                }
            }
            #pragma unroll
            for (int c = 0; c < 2; c++) {
                h1m2[c]=h1m1[c]; h1m1[c]=h1[c]; h1dm2[c]=h1dm1[c]; h1dm1[c]=h1d[c];
                h2m2[c]=h2m1[c]; h2m1[c]=h2[c]; h2dm2[c]=h2dm1[c]; h2dm1[c]=h2d[c];
                h3m2[c]=h3m1[c]; h3m1[c]=h3[c]; h3dm2[c]=h3dm1[c]; h3dm1[c]=h3d[c];
                ad2[c]=ad1[c];   ad1[c]=a[c];
                e1d2[c]=e1d1[c]; e1d1[c]=e1[c];
                e2d2[c]=e2d1[c]; e2d1[c]=e2[c];
                mk0d2[c]=mk0d1[c]; mk0d1[c]=mk0[c]; mk1d1[c]=mk1[c];
            }
        }
    }
}

template<bool FIRST>
__global__ __launch_bounds__(128) void triple_kernel(
    const float* __restrict__ pred,
    const float* __restrict__ target,
    int srcbuf, int dstbuf)
{
    const int z     = blockIdx.z;
    const int skel  = z >> 4;
    const int plane = z & 15;
    const int wtile = blockIdx.x * 4 + (threadIdx.x >> 5);
    if (wtile >= NTILES) return;
    const int lane = threadIdx.x & 31;
    const int gx0  = wtile * TCOLS - 4 + 2 * lane;
    const int y0   = blockIdx.y * STRIP;

    const size_t pbase = (size_t)plane * PLANE_SZ;
    const float* src = FIRST ? ((skel ? target : pred) + pbase)
                             : (const float*)&g_E[skel][srcbuf][pbase];
    float* dst = &g_E[skel][dstbuf][pbase];
    float* acc = &g_acc[skel][pbase];

    // fast path: loads touch rows [y0-4, y0+STRIP+7] and cols [gx0_base, +63]
    const bool fast = (wtile >= 1) & (wtile <= 17) &
                      (y0 >= 4) & (y0 + STRIP + 7 <= IMG_H - 1);
    if (fast) triple_sweep<FIRST, false>(src, dst, acc, skel, gx0, y0, lane);
    else      triple_sweep<FIRST, true >(src, dst, acc, skel, gx0, y0, lane);
}

// ---------------------------------------------------------------------------
// Final sweep: steps 9,10 fused with reduction.
// ---------------------------------------------------------------------------
template<bool MASK>
__device__ __forceinline__ void final_sweep(
    const float* __restrict__ src,
    const float* __restrict__ acc,
    const float* __restrict__ other,
    int skel, int gx0, int y0, int lane,
    float& s_num, float& s_den)
{
    const int  yEnd = y0 + STRIP;
    const bool outL = (lane >= 2) & (lane <= 29);
    bool inc[2];
    inc[0] = !MASK || ((unsigned)gx0       < (unsigned)IMG_W);
    inc[1] = !MASK || ((unsigned)(gx0 + 1) < (unsigned)IMG_W);

    float h1m1[2]={}, h1m2[2]={}, h1dm1[2]={}, h1dm2[2]={};
    float h2m1[2]={}, h2m2[2]={}, h2dm1[2]={}, h2dm2[2]={};
    float ad1[2]={}, ad2[2]={}, e1d1[2]={}, e1d2[2]={}, mkd1[2]={};

    float abuf[4][2];
    float accbuf[4][2] = {}, obuf[4][2] = {};

    auto ldrow = [&](int rr, float v[2]) {
        if (MASK) {
            v[0] = 1e30f; v[1] = 1e30f;
            bool rv = (unsigned)rr < (unsigned)IMG_H;
            if (rv & inc[0]) v[0] = __ldg(&src[(size_t)rr * IMG_W + gx0]);
            if (rv & inc[1]) v[1] = __ldg(&src[(size_t)rr * IMG_W + gx0 + 1]);
        } else {
            float2 t = *reinterpret_cast<const float2*>(&src[(size_t)rr * IMG_W + gx0]);
            v[0] = t.x; v[1] = t.y;
        }
    };

    #pragma unroll
    for (int j = 0; j < 4; j++) ldrow(y0 - 4 + j, abuf[j]);

    for (int rb = y0 - 4; rb <= yEnd; rb += 4) {
        #pragma unroll
        for (int j = 0; j < 4; j++) {
            const int r = rb + j;
            float a[2] = { abuf[j][0], abuf[j][1] };
            ldrow(r + 4, abuf[j]);
            // consume row r-3 (slot (j+1)&3), prefetch row r (slot j)
            float av[2] = { accbuf[(j + 1) & 3][0], accbuf[(j + 1) & 3][1] };
            float ov[2] = { obuf[(j + 1) & 3][0],  obuf[(j + 1) & 3][1] };
            if ((r >= y0) & (r < yEnd) & outL) {
                if (MASK) {
                    if (inc[0]) { accbuf[j][0] = acc[(size_t)r * IMG_W + gx0];
                                  obuf[j][0]   = __ldg(&other[(size_t)r * IMG_W + gx0]); }
                    if (inc[1]) { accbuf[j][1] = acc[(size_t)r * IMG_W + gx0 + 1];
                                  obuf[j][1]   = __ldg(&other[(size_t)r * IMG_W + gx0 + 1]); }
                } else {
                    float2 t = *reinterpret_cast<const float2*>(&acc[(size_t)r * IMG_W + gx0]);
                    accbuf[j][0] = t.x; accbuf[j][1] = t.y;
                    float2 u = *reinterpret_cast<const float2*>(&other[(size_t)r * IMG_W + gx0]);
                    obuf[j][0] = u.x; obuf[j][1] = u.y;
                }
            }

            float h1[2]; hpmin(a, h1);                    // row r (E9)
            float e1[2], e1dv[2], e1ev[2];
            const bool m1 = !MASK || ((unsigned)(r - 1) < (unsigned)IMG_H);
            #pragma unroll
            for (int c = 0; c < 2; c++) {
                e1[c] = min3f(h1m2[c], h1m1[c], h1[c]);   // E10, row r-1
                bool mm = m1 & inc[c];
                e1dv[c] = mm ? e1[c] : -1e30f;
                e1ev[c] = mm ? e1[c] :  1e30f;
            }
            float h1d[2]; hpmax(e1dv, h1d);
            float h2[2];  hpmin(e1ev, h2);
            float mk[2], e2[2], e2dv[2];
            const bool m2 = !MASK || ((unsigned)(r - 2) < (unsigned)IMG_H);
            #pragma unroll
            for (int c = 0; c < 2; c++) {
                float d1 = max3f(h1dm2[c], h1dm1[c], h1d[c]);  // dilate(E10), r-2
                mk[c] = 1.f - fmaxf(ad2[c] - d1, 0.f);         // 1-delta9, r-2
                e2[c] = min3f(h2m2[c], h2m1[c], h2[c]);        // E11, r-2
                bool mm = m2 & inc[c];
                e2dv[c] = mm ? e2[c] : -1e30f;
            }
            float h2d[2]; hpmax(e2dv, h2d);
            const int ro = r - 3;
            if (outL & (ro >= y0) & (ro < yEnd)) {
                #pragma unroll
                for (int c = 0; c < 2; c++) {
                    if (!MASK || inc[c]) {
                        float d2 = max3f(h2dm2[c], h2dm1[c], h2d[c]);  // dilate(E11), r-3
                        float dl = fmaxf(e1d2[c] - d2, 0.f);           // delta10, r-3
                        float sp = 1.f - av[c] * (mkd1[c] * (1.f - dl));
                        s_num += sp * (skel ? sigmoidf(ov[c]) : ov[c]);
                        s_den += sp;
                    }
                }
            }
            #pragma unroll
            for (int c = 0; c < 2; c++) {
                h1m2[c]=h1m1[c]; h1m1[c]=h1[c]; h1dm2[c]=h1dm1[c]; h1dm1[c]=h1d[c];
                h2m2[c]=h2m1[c]; h2m1[c]=h2[c]; h2dm2[c]=h2dm1[c]; h2dm1[c]=h2d[c];
                ad2[c]=ad1[c];   ad1[c]=a[c];
                e1d2[c]=e1d1[c]; e1d1[c]=e1[c]; mkd1[c]=mk[c];
            }
        }
    }
}

__global__ __launch_bounds__(128) void final_kernel(
    const float* __restrict__ pred,
    const float* __restrict__ target,
    int srcbuf)
{
    const int z     = blockIdx.z;
    const int skel  = z >> 4;
    const int plane = z & 15;
    const int wtile = blockIdx.x * 4 + (threadIdx.x >> 5);
    const int lane  = threadIdx.x & 31;
    const int y0    = blockIdx.y * STRIP;

    float s_num = 0.f, s_den = 0.f;

    if (wtile < NTILES) {
        const int gx0 = wtile * TCOLS - 4 + 2 * lane;
        const size_t pbase = (size_t)plane * PLANE_SZ;
        const float* src   = &g_E[skel][srcbuf][pbase];
        const float* acc   = &g_acc[skel][pbase];
        // skel_p pairs with raw target; skel_t pairs with sigmoid(pred)
        const float* other = (skel ? pred : target) + pbase;
        const bool fast = (wtile >= 1) & (wtile <= 17) &
                          (y0 >= 4) & (y0 + STRIP + 7 <= IMG_H - 1);
        if (fast) final_sweep<false>(src, acc, other, skel, gx0, y0, lane, s_num, s_den);
        else      final_sweep<true >(src, acc, other, skel, gx0, y0, lane, s_num, s_den);
    }

    #pragma unroll
    for (int off = 16; off; off >>= 1) {
        s_num += __shfl_down_sync(0xffffffffu, s_num, off);
        s_den += __shfl_down_sync(0xffffffffu, s_den, off);
    }
    __shared__ float red[4][2];
    int warp = threadIdx.x >> 5;
    if ((threadIdx.x & 31) == 0) { red[warp][0] = s_num; red[warp][1] = s_den; }
    __syncthreads();
    if (threadIdx.x < 2) {
        float s = red[0][threadIdx.x] + red[1][threadIdx.x]
                + red[2][threadIdx.x] + red[3][threadIdx.x];
        atomicAdd(&g_sums[plane * 4 + skel * 2 + threadIdx.x], s);
    }
}

__global__ void finalize_kernel(float* __restrict__ out) {
    if (threadIdx.x == 0 && blockIdx.x == 0) {
        const float eps = 1e-6f;
        float total = 0.f;
        #pragma unroll
        for (int pl = 0; pl < NPLANES; pl++) {
            float spt = g_sums[pl * 4 + 0];
            float sp  = g_sums[pl * 4 + 1];
            float stp = g_sums[pl * 4 + 2];
            float st  = g_sums[pl * 4 + 3];
            float tprec = spt / (sp + eps);
            float tsens = stp / (st + eps);
            total += 1.0f - 2.0f * tprec * tsens / (tprec + tsens + eps);
        }
        out[0] = total * (1.0f / (float)NPLANES);
    }
}

extern "C" void kernel_launch(void* const* d_in, const int* in_sizes, int n_in,
                              void* d_out, int out_size)
{
    (void)in_sizes; (void)n_in; (void)out_size;
    const float* pred   = (const float*)d_in[0];
    const float* target = (const float*)d_in[1];
    float* out = (float*)d_out;

    zero_sums_kernel<<<1, 64>>>();

    dim3 grid((NTILES + 3) / 4, IMG_H / STRIP, NPLANES * 2);   // 5 x 8 x 32
    dim3 blk(128);

    // steps 0-2 -> E3 (buf0); 3-5 -> E6 (buf1); 6-8 -> E9 (buf0); 9-10 + reduce
    triple_kernel<true ><<<grid, blk>>>(pred, target, 0, 0);
    triple_kernel<false><<<grid, blk>>>(pred, target, 0, 1);
    triple_kernel<false><<<grid, blk>>>(pred, target, 1, 0);
    final_kernel<<<grid, blk>>>(pred, target, 0);

    finalize_kernel<<<1, 32>>>(out);
}

// round 9
// speedup vs baseline: 1.1979x; 1.1979x over previous
#include <cuda_runtime.h>

// SoftCLDiceLoss on [8,2,1024,1024]:
//   p = sigmoid(pred), t = target
//   skel(x) = 1 - prod_{k=0..10} (1 - relu(E_k - dilate(E_{k+1}))),  E_k = erode^k(clip(x))
//   erode = 3x3 min (pad +inf), dilate = 3x3 max (pad -inf)
//   tprec = sum(skel_p*t)/(sum(skel_p)+eps); tsens = sum(skel_t*p)/(sum(skel_t)+eps)
//   loss = mean(1 - 2*tprec*tsens/(tprec+tsens+eps))
//
// R8: R4 warp-strip register sweep (1 col/lane, 53 regs) + interior fast path:
// mask-free specialization with shared shuffle pairs (8 shuffles/row vs 12).
// 3 erosion steps fused per kernel, final 2 steps fused with the reduction.

#define IMG_W    1024
#define IMG_H    1024
#define NPLANES  16
#define PLANE_SZ (IMG_W * IMG_H)

#define STRIP   128
#define COLS3   24             // 32 - 2*4 halo (triple kernel)
#define TILES3  43             // ceil(1024/24)
#define COLS2   26             // 32 - 2*3 halo (final kernel)
#define TILES2  40             // ceil(1024/26)

__device__ float g_E[2][2][NPLANES * PLANE_SZ];   // [skel][pingpong]
__device__ float g_acc[2][NPLANES * PLANE_SZ];
__device__ float g_sums[NPLANES * 4];

__device__ __forceinline__ float min3f(float a, float b, float c) { return fminf(a, fminf(b, c)); }
__device__ __forceinline__ float max3f(float a, float b, float c) { return fmaxf(a, fmaxf(b, c)); }
__device__ __forceinline__ float sigmoidf(float x) { return 1.0f / (1.0f + __expf(-x)); }

__device__ __forceinline__ float hmin3(float v) {
    float l = __shfl_up_sync(0xffffffffu, v, 1);
    float r = __shfl_down_sync(0xffffffffu, v, 1);
    return min3f(l, v, r);
}
__device__ __forceinline__ float hmax3(float v) {
    float l = __shfl_up_sync(0xffffffffu, v, 1);
    float r = __shfl_down_sync(0xffffffffu, v, 1);
    return max3f(l, v, r);
}
// one shuffle pair feeding both min and max (fast path)
__device__ __forceinline__ void hshfl(float v, float& l, float& r) {
    l = __shfl_up_sync(0xffffffffu, v, 1);
    r = __shfl_down_sync(0xffffffffu, v, 1);
}

__global__ void zero_sums_kernel() {
    int i = threadIdx.x;
    if (i < NPLANES * 4) g_sums[i] = 0.0f;
}

// ---------------------------------------------------------------------------
// Triple sweep, masked (edge tiles/strips) — identical logic to R4.
// ---------------------------------------------------------------------------
template<bool FIRST>
__device__ __forceinline__ void triple_sweep_masked(
    const float* __restrict__ src, float* __restrict__ dst, float* __restrict__ acc,
    int skel, int gx, int y0, int lane)
{
    const int  yEnd = y0 + STRIP;
    const bool inX  = (unsigned)gx < (unsigned)IMG_W;
    const bool outL = (lane >= 4) & (lane <= 27) & inX;

    auto ldrow = [&](int rr) -> float {
        float v = 1e30f;
        if (((unsigned)rr < (unsigned)IMG_H) & inX) {
            float x = __ldg(&src[(size_t)rr * IMG_W + gx]);
            v = FIRST ? (skel ? __saturatef(x) : sigmoidf(x)) : x;
        }
        return v;
    };

    float abuf[4];
    float accbuf[4] = {0.f, 0.f, 0.f, 0.f};
    #pragma unroll
    for (int j = 0; j < 4; j++) abuf[j] = ldrow(y0 - 4 + j);

    float h1m1=0,h1m2=0,h1dm1=0,h1dm2=0;
    float h2m1=0,h2m2=0,h2dm1=0,h2dm2=0;
    float h3m1=0,h3m2=0,h3dm1=0,h3dm2=0;
    float ad1=0,ad2=0,e1d1=0,e1d2=0,e2d1=0,e2d2=0;
    float mk0d1=0,mk0d2=0,mk1d1=0;

    for (int rb = y0 - 4; rb <= yEnd; rb += 4) {
        #pragma unroll
        for (int j = 0; j < 4; j++) {
            const int r = rb + j;
            float a = abuf[j];
            abuf[j] = ldrow(r + 4);
            float av = 0.f;
            if (!FIRST) {
                av = accbuf[j];
                if ((r >= y0) & (r < yEnd) & outL)
                    accbuf[j] = acc[(size_t)r * IMG_W + gx];
            }

            float h1 = hmin3(a);
            float e1 = min3f(h1m2, h1m1, h1);
            bool  m1 = ((unsigned)(r - 1) < (unsigned)IMG_H) & inX;
            float h1d = hmax3(m1 ? e1 : -1e30f);
            float h2  = hmin3(m1 ? e1 :  1e30f);
            float d1  = max3f(h1dm2, h1dm1, h1d);
            float mk0 = 1.f - fmaxf(ad2 - d1, 0.f);
            float e2  = min3f(h2m2, h2m1, h2);
            bool  m2 = ((unsigned)(r - 2) < (unsigned)IMG_H) & inX;
            float h2d = hmax3(m2 ? e2 : -1e30f);
            float h3  = hmin3(m2 ? e2 :  1e30f);
            float d2  = max3f(h2dm2, h2dm1, h2d);
            float mk1 = 1.f - fmaxf(e1d2 - d2, 0.f);
            float e3  = min3f(h3m2, h3m1, h3);
            bool  m3 = ((unsigned)(r - 3) < (unsigned)IMG_H) & inX;
            if (outL & (r - 3 >= y0) & (r - 3 < yEnd))
                dst[(size_t)(r - 3) * IMG_W + gx] = e3;
            float h3d = hmax3(m3 ? e3 : -1e30f);
            float d3  = max3f(h3dm2, h3dm1, h3d);
            float mk2 = 1.f - fmaxf(e2d2 - d3, 0.f);
            const int ro = r - 4;
            if (outL & (ro >= y0) & (ro < yEnd)) {
                float m = mk0d2 * mk1d1 * mk2;
                acc[(size_t)ro * IMG_W + gx] = FIRST ? m : av * m;
            }
            h1m2=h1m1;  h1m1=h1;  h1dm2=h1dm1; h1dm1=h1d;
            h2m2=h2m1;  h2m1=h2;  h2dm2=h2dm1; h2dm1=h2d;
            h3m2=h3m1;  h3m1=h3;  h3dm2=h3dm1; h3dm1=h3d;
            ad2=ad1;   ad1=a;   e1d2=e1d1;  e1d1=e1;  e2d2=e2d1; e2d1=e2;
            mk0d2=mk0d1; mk0d1=mk0; mk1d1=mk1;
        }
    }
}

// ---------------------------------------------------------------------------
// Triple sweep, fast (interior): no bounds, no selects, shared shuffle pairs.
// Valid only when all touched rows [y0-4, y0+STRIP+7] and cols [gx0-?, +31]
// are inside the image (checked by caller).
// ---------------------------------------------------------------------------
template<bool FIRST>
__device__ __forceinline__ void triple_sweep_fast(
    const float* __restrict__ src, float* __restrict__ dst, float* __restrict__ acc,
    int skel, int gx, int y0, int lane)
{
    const int  yEnd = y0 + STRIP;
    const bool outL = (lane >= 4) & (lane <= 27);

    auto ldrow = [&](int rr) -> float {
        float x = __ldg(&src[(size_t)rr * IMG_W + gx]);
        return FIRST ? (skel ? __saturatef(x) : sigmoidf(x)) : x;
    };

    float abuf[4];
    float accbuf[4] = {0.f, 0.f, 0.f, 0.f};
    #pragma unroll
    for (int j = 0; j < 4; j++) abuf[j] = ldrow(y0 - 4 + j);

    float h1m1=0,h1m2=0,h1dm1=0,h1dm2=0;
    float h2m1=0,h2m2=0,h2dm1=0,h2dm2=0;
    float h3m1=0,h3m2=0,h3dm1=0,h3dm2=0;
    float ad1=0,ad2=0,e1d1=0,e1d2=0,e2d1=0,e2d2=0;
    float mk0d1=0,mk0d2=0,mk1d1=0;

    for (int rb = y0 - 4; rb <= yEnd; rb += 4) {
        #pragma unroll
        for (int j = 0; j < 4; j++) {
            const int r = rb + j;
            float a = abuf[j];
            abuf[j] = ldrow(r + 4);
            float av = 0.f;
            if (!FIRST) {
                av = accbuf[j];
                accbuf[j] = acc[(size_t)r * IMG_W + gx];   // rows all in-plane here
            }

            float l, rr_;
            hshfl(a, l, rr_);
            float h1 = min3f(l, a, rr_);
            float e1 = min3f(h1m2, h1m1, h1);
            hshfl(e1, l, rr_);                      // shared: feeds dilate AND erode
            float h1d = max3f(l, e1, rr_);
            float h2  = min3f(l, e1, rr_);
            float d1  = max3f(h1dm2, h1dm1, h1d);
            float mk0 = 1.f - fmaxf(ad2 - d1, 0.f);
            float e2  = min3f(h2m2, h2m1, h2);
            hshfl(e2, l, rr_);
            float h2d = max3f(l, e2, rr_);
            float h3  = min3f(l, e2, rr_);
            float d2  = max3f(h2dm2, h2dm1, h2d);
            float mk1 = 1.f - fmaxf(e1d2 - d2, 0.f);
            float e3  = min3f(h3m2, h3m1, h3);
            if (outL & ((unsigned)(r - 3 - y0) < (unsigned)STRIP))
                dst[(size_t)(r - 3) * IMG_W + gx] = e3;
            hshfl(e3, l, rr_);
            float h3d = max3f(l, e3, rr_);
            float d3  = max3f(h3dm2, h3dm1, h3d);
            float mk2 = 1.f - fmaxf(e2d2 - d3, 0.f);
            const int ro = r - 4;
            if (outL & ((unsigned)(ro - y0) < (unsigned)STRIP)) {
                float m = mk0d2 * mk1d1 * mk2;
                acc[(size_t)ro * IMG_W + gx] = FIRST ? m : av * m;
            }
            h1m2=h1m1;  h1m1=h1;  h1dm2=h1dm1; h1dm1=h1d;
            h2m2=h2m1;  h2m1=h2;  h2dm2=h2dm1; h2dm1=h2d;
            h3m2=h3m1;  h3m1=h3;  h3dm2=h3dm1; h3dm1=h3d;
            ad2=ad1;   ad1=a;   e1d2=e1d1;  e1d1=e1;  e2d2=e2d1; e2d1=e2;
            mk0d2=mk0d1; mk0d1=mk0; mk1d1=mk1;
        }
    }
}

template<bool FIRST>
__global__ __launch_bounds__(128) void triple_kernel(
    const float* __restrict__ pred,
    const float* __restrict__ target,
    int srcbuf, int dstbuf)
{
    const int z     = blockIdx.z;
    const int skel  = z >> 4;
    const int plane = z & 15;
    const int wtile = blockIdx.x * 4 + (threadIdx.x >> 5);
    if (wtile >= TILES3) return;
    const int lane = threadIdx.x & 31;
    const int gx   = wtile * COLS3 - 4 + lane;
    const int y0   = blockIdx.y * STRIP;

    const size_t pbase = (size_t)plane * PLANE_SZ;
    const float* src = FIRST ? ((skel ? target : pred) + pbase)
                             : (const float*)&g_E[skel][srcbuf][pbase];
    float* dst = &g_E[skel][dstbuf][pbase];
    float* acc = &g_acc[skel][pbase];

    // fast: cols [wtile*24-4, wtile*24+27] in [0,1024) and rows [y0-4, y0+STRIP+7] in [0,1024)
    const bool fast = (wtile >= 1) & (wtile <= 41) &
                      (y0 >= 4) & (y0 + STRIP + 7 < IMG_H);
    if (fast) triple_sweep_fast<FIRST>(src, dst, acc, skel, gx, y0, lane);
    else      triple_sweep_masked<FIRST>(src, dst, acc, skel, gx, y0, lane);
}

// ---------------------------------------------------------------------------
// Final sweep (steps 9,10 + reduction), masked — identical logic to R4.
// ---------------------------------------------------------------------------
__device__ __forceinline__ void final_sweep_masked(
    const float* __restrict__ src, const float* __restrict__ acc,
    const float* __restrict__ other,
    int skel, int gx, int y0, int lane, float& s_num, float& s_den)
{
    const int  yEnd = y0 + STRIP;
    const bool inX  = (unsigned)gx < (unsigned)IMG_W;
    const bool outL = (lane >= 3) & (lane <= 28) & inX;

    auto ldrow = [&](int rr) -> float {
        float v = 1e30f;
        if (((unsigned)rr < (unsigned)IMG_H) & inX)
            v = __ldg(&src[(size_t)rr * IMG_W + gx]);
        return v;
    };

    float abuf[4];
    float accbuf[4] = {0.f, 0.f, 0.f, 0.f};
    float obuf[4]   = {0.f, 0.f, 0.f, 0.f};
    #pragma unroll
    for (int j = 0; j < 4; j++) abuf[j] = ldrow(y0 - 4 + j);

    float h1m1=0,h1m2=0,h1dm1=0,h1dm2=0;
    float h2m1=0,h2m2=0,h2dm1=0,h2dm2=0;
    float ad1=0,ad2=0,e1d1=0,e1d2=0,mkd1=0;

    for (int rb = y0 - 4; rb <= yEnd; rb += 4) {
        #pragma unroll
        for (int j = 0; j < 4; j++) {
            const int r = rb + j;
            float a = abuf[j];
            abuf[j] = ldrow(r + 4);
            float av = accbuf[(j + 1) & 3];
            float ov = obuf[(j + 1) & 3];
            if ((r >= y0) & (r < yEnd) & outL) {
                size_t g = (size_t)r * IMG_W + gx;
                accbuf[j] = acc[g];
                obuf[j]   = __ldg(&other[g]);
            }

            float h1 = hmin3(a);
            float e1 = min3f(h1m2, h1m1, h1);
            bool  m1 = ((unsigned)(r - 1) < (unsigned)IMG_H) & inX;
            float h1d = hmax3(m1 ? e1 : -1e30f);
            float h2  = hmin3(m1 ? e1 :  1e30f);
            float d1  = max3f(h1dm2, h1dm1, h1d);
            float mk  = 1.f - fmaxf(ad2 - d1, 0.f);
            float e2  = min3f(h2m2, h2m1, h2);
            bool  m2 = ((unsigned)(r - 2) < (unsigned)IMG_H) & inX;
            float h2d = hmax3(m2 ? e2 : -1e30f);
            float d2  = max3f(h2dm2, h2dm1, h2d);
            float dl  = fmaxf(e1d2 - d2, 0.f);
            const int ro = r - 3;
            if (outL & (ro >= y0) & (ro < yEnd)) {
                float sp = 1.f - av * (mkd1 * (1.f - dl));
                s_num += sp * (skel ? sigmoidf(ov) : ov);
                s_den += sp;
            }
            h1m2=h1m1;  h1m1=h1;  h1dm2=h1dm1; h1dm1=h1d;
            h2m2=h2m1;  h2m1=h2;  h2dm2=h2dm1; h2dm1=h2d;
            ad2=ad1;   ad1=a;   e1d2=e1d1;  e1d1=e1;  mkd1=mk;
        }
    }
}

// Fast interior variant: no bounds, shared shuffles, unconditional prefetch.
__device__ __forceinline__ void final_sweep_fast(
    const float* __restrict__ src, const float* __restrict__ acc,
    const float* __restrict__ other,
    int skel, int gx, int y0, int lane, float& s_num, float& s_den)
{
    const int  yEnd = y0 + STRIP;
    const bool outL = (lane >= 3) & (lane <= 28);

    auto ldrow = [&](int rr) -> float {
        return __ldg(&src[(size_t)rr * IMG_W + gx]);
    };

    float abuf[4];
    float accbuf[4] = {0.f, 0.f, 0.f, 0.f};
    float obuf[4]   = {0.f, 0.f, 0.f, 0.f};
    #pragma unroll
    for (int j = 0; j < 4; j++) abuf[j] = ldrow(y0 - 4 + j);

    float h1m1=0,h1m2=0,h1dm1=0,h1dm2=0;
    float h2m1=0,h2m2=0,h2dm1=0,h2dm2=0;
    float ad1=0,ad2=0,e1d1=0,e1d2=0,mkd1=0;

    for (int rb = y0 - 4; rb <= yEnd; rb += 4) {
        #pragma unroll
        for (int j = 0; j < 4; j++) {
            const int r = rb + j;
            float a = abuf[j];
            abuf[j] = ldrow(r + 4);
            float av = accbuf[(j + 1) & 3];
            float ov = obuf[(j + 1) & 3];
            {
                size_t g = (size_t)r * IMG_W + gx;     // rows all in-plane here
                accbuf[j] = acc[g];
                obuf[j]   = __ldg(&other[g]);
            }

            float l, rr_;
            hshfl(a, l, rr_);
            float h1 = min3f(l, a, rr_);
            float e1 = min3f(h1m2, h1m1, h1);
            hshfl(e1, l, rr_);
            float h1d = max3f(l, e1, rr_);
            float h2  = min3f(l, e1, rr_);
            float d1  = max3f(h1dm2, h1dm1, h1d);
            float mk  = 1.f - fmaxf(ad2 - d1, 0.f);
            float e2  = min3f(h2m2, h2m1, h2);
            hshfl(e2, l, rr_);
            float h2d = max3f(l, e2, rr_);
            float d2  = max3f(h2dm2, h2dm1, h2d);
            float dl  = fmaxf(e1d2 - d2, 0.f);
            const int ro = r - 3;
            if (outL & ((unsigned)(ro - y0) < (unsigned)STRIP)) {
                float sp = 1.f - av * (mkd1 * (1.f - dl));
                s_num += sp * (skel ? sigmoidf(ov) : ov);
                s_den += sp;
            }
            h1m2=h1m1;  h1m1=h1;  h1dm2=h1dm1; h1dm1=h1d;
            h2m2=h2m1;  h2m1=h2;  h2dm2=h2dm1; h2dm1=h2d;
            ad2=ad1;   ad1=a;   e1d2=e1d1;  e1d1=e1;  mkd1=mk;
        }
    }
}

__global__ __launch_bounds__(128) void final_kernel(
    const float* __restrict__ pred,
    const float* __restrict__ target,
    int srcbuf)
{
    const int z     = blockIdx.z;
    const int skel  = z >> 4;
    const int plane = z & 15;
    const int wtile = blockIdx.x * 4 + (threadIdx.x >> 5);
    const int lane  = threadIdx.x & 31;
    const int y0    = blockIdx.y * STRIP;

    float s_num = 0.f, s_den = 0.f;

    if (wtile < TILES2) {
        const int gx = wtile * COLS2 - 3 + lane;
        const size_t pbase = (size_t)plane * PLANE_SZ;
        const float* src   = &g_E[skel][srcbuf][pbase];
        const float* acc   = &g_acc[skel][pbase];
        // skel_p pairs with raw target; skel_t pairs with sigmoid(pred)
        const float* other = (skel ? pred : target) + pbase;
        // fast: cols [wtile*26-3, wtile*26+28] in [0,1024), rows [y0-4, y0+STRIP+7] in [0,1024)
        const bool fast = (wtile >= 1) & (wtile <= 38) &
                          (y0 >= 4) & (y0 + STRIP + 7 < IMG_H);
        if (fast) final_sweep_fast(src, acc, other, skel, gx, y0, lane, s_num, s_den);
        else      final_sweep_masked(src, acc, other, skel, gx, y0, lane, s_num, s_den);
    }

    #pragma unroll
    for (int off = 16; off; off >>= 1) {
        s_num += __shfl_down_sync(0xffffffffu, s_num, off);
        s_den += __shfl_down_sync(0xffffffffu, s_den, off);
    }
    __shared__ float red[4][2];
    int warp = threadIdx.x >> 5;
    if ((threadIdx.x & 31) == 0) { red[warp][0] = s_num; red[warp][1] = s_den; }
    __syncthreads();
    if (threadIdx.x < 2) {
        float s = red[0][threadIdx.x] + red[1][threadIdx.x]
                + red[2][threadIdx.x] + red[3][threadIdx.x];
        atomicAdd(&g_sums[plane * 4 + skel * 2 + threadIdx.x], s);
    }
}

__global__ void finalize_kernel(float* __restrict__ out) {
    if (threadIdx.x == 0 && blockIdx.x == 0) {
        const float eps = 1e-6f;
        float total = 0.f;
        #pragma unroll
        for (int pl = 0; pl < NPLANES; pl++) {
            float spt = g_sums[pl * 4 + 0];
            float sp  = g_sums[pl * 4 + 1];
            float stp = g_sums[pl * 4 + 2];
            float st  = g_sums[pl * 4 + 3];
            float tprec = spt / (sp + eps);
            float tsens = stp / (st + eps);
            total += 1.0f - 2.0f * tprec * tsens / (tprec + tsens + eps);
        }
        out[0] = total * (1.0f / (float)NPLANES);
    }
}

extern "C" void kernel_launch(void* const* d_in, const int* in_sizes, int n_in,
                              void* d_out, int out_size)
{
    (void)in_sizes; (void)n_in; (void)out_size;
    const float* pred   = (const float*)d_in[0];
    const float* target = (const float*)d_in[1];
    float* out = (float*)d_out;

    zero_sums_kernel<<<1, 64>>>();

    dim3 tgrid((TILES3 + 3) / 4, IMG_H / STRIP, NPLANES * 2);   // 11 x 8 x 32
    dim3 fgrid((TILES2 + 3) / 4, IMG_H / STRIP, NPLANES * 2);   // 10 x 8 x 32
    dim3 blk(128);

    // steps 0-2 -> E3 (buf0); 3-5 -> E6 (buf1); 6-8 -> E9 (buf0); 9-10 + reduce
    triple_kernel<true ><<<tgrid, blk>>>(pred, target, 0, 0);
    triple_kernel<false><<<tgrid, blk>>>(pred, target, 0, 1);
    triple_kernel<false><<<tgrid, blk>>>(pred, target, 1, 0);
    final_kernel<<<fgrid, blk>>>(pred, target, 0);

    finalize_kernel<<<1, 32>>>(out);
}